// round 1
// baseline (speedup 1.0000x reference)
#include <cuda_runtime.h>
#include <math.h>

// Problem constants (fixed by the reference setup_inputs)
#define B_    16
#define CIN   512
#define T_    2048
#define H_    2048
#define COUT  512
#define G_    4
#define K1    (CIN / G_)   // 128
#define K2    (H_  / G_)   // 512

// GEMM tiling
#define BM 128
#define BN 128
#define BK 32
#define SS 132   // smem row stride (floats): 16B-aligned, breaks worst bank conflicts

// Scratch for the shuffled+activated intermediate: [B, H, T] fp32 = 256 MiB
__device__ float g_h[(size_t)B_ * H_ * T_];

__device__ __forceinline__ float gelu_exact(float v) {
    return 0.5f * v * (1.0f + erff(v * 0.70710678118654752440f));
}

// ---------------------------------------------------------------------------
// Kernel 1: h = shuffle(gelu(grouped_pw(x*mask, w1, b1)))  -> g_h
// Grid: (T/BN, H/BM, B). CTA computes a 128x128 (channels x t) tile.
// ---------------------------------------------------------------------------
__global__ __launch_bounds__(256, 2)
void ffn_layer1(const float* __restrict__ x, const float* __restrict__ xm,
                const float* __restrict__ w1, const float* __restrict__ b1)
{
    __shared__ float Ws[BK * SS];   // Ws[k][m], k-major
    __shared__ float Xs[BK * SS];   // Xs[k][c], k-major

    const int t0 = blockIdx.x * BN;
    const int m0 = blockIdx.y * BM;
    const int b  = blockIdx.z;
    const int g  = m0 / (H_ / G_);          // 512 h-channels per group, BM|512

    const int tid = threadIdx.x;
    const int tm  = tid & 15;               // row group: rows tm*8..tm*8+7
    const int tn  = tid >> 4;               // col group: cols tn*8..tn*8+7

    const float* xg   = x  + ((size_t)b * CIN + (size_t)g * K1) * T_ + t0;
    const float* mrow = xm + (size_t)b * T_ + t0;

    float acc[8][8];
    #pragma unroll
    for (int i = 0; i < 8; i++)
        #pragma unroll
        for (int j = 0; j < 8; j++) acc[i][j] = 0.f;

    for (int kk = 0; kk < K1; kk += BK) {
        // --- stage W1 chunk (rows m0..m0+127, cols kk..kk+31), transposed ---
        #pragma unroll
        for (int it = 0; it < 4; it++) {
            int idx = it * 256 + tid;       // 1024 float4s
            int r   = idx >> 3;             // 0..127 (row within tile)
            int c4  = idx & 7;              // 0..7   (float4 along K)
            float4 v = *(const float4*)(w1 + (size_t)(m0 + r) * K1 + kk + c4 * 4);
            Ws[(c4 * 4 + 0) * SS + r] = v.x;
            Ws[(c4 * 4 + 1) * SS + r] = v.y;
            Ws[(c4 * 4 + 2) * SS + r] = v.z;
            Ws[(c4 * 4 + 3) * SS + r] = v.w;
        }
        // --- stage X chunk (channels kk..kk+31 within group, cols t0..t0+127) ---
        #pragma unroll
        for (int it = 0; it < 4; it++) {
            int idx = it * 256 + tid;
            int r   = idx >> 5;             // 0..31
            int c4  = idx & 31;             // 0..31
            float4 v = *(const float4*)(xg + (size_t)(kk + r) * T_ + c4 * 4);
            float4 m = *(const float4*)(mrow + c4 * 4);
            v.x *= m.x; v.y *= m.y; v.z *= m.z; v.w *= m.w;
            *(float4*)(Xs + r * SS + c4 * 4) = v;
        }
        __syncthreads();

        #pragma unroll
        for (int k = 0; k < BK; k++) {
            float4 a0 = *(const float4*)(Ws + k * SS + tm * 8);
            float4 a1 = *(const float4*)(Ws + k * SS + tm * 8 + 4);
            float4 c0 = *(const float4*)(Xs + k * SS + tn * 8);
            float4 c1 = *(const float4*)(Xs + k * SS + tn * 8 + 4);
            float a[8] = {a0.x, a0.y, a0.z, a0.w, a1.x, a1.y, a1.z, a1.w};
            float c[8] = {c0.x, c0.y, c0.z, c0.w, c1.x, c1.y, c1.z, c1.w};
            #pragma unroll
            for (int i = 0; i < 8; i++)
                #pragma unroll
                for (int j = 0; j < 8; j++)
                    acc[i][j] = fmaf(a[i], c[j], acc[i][j]);
        }
        __syncthreads();
    }

    // Epilogue: bias + exact GELU, write channel-shuffled: c' = (m%512)*4 + g
    #pragma unroll
    for (int i = 0; i < 8; i++) {
        int   m    = m0 + tm * 8 + i;
        float bias = b1[m];
        int   j    = m & (K2 - 1);          // m % 512
        int   cs   = j * G_ + g;
        float* orow = g_h + ((size_t)b * H_ + cs) * T_ + t0 + tn * 8;
        float v[8];
        #pragma unroll
        for (int jj = 0; jj < 8; jj++)
            v[jj] = gelu_exact(acc[i][jj] + bias);
        *(float4*)(orow)     = make_float4(v[0], v[1], v[2], v[3]);
        *(float4*)(orow + 4) = make_float4(v[4], v[5], v[6], v[7]);
    }
}

// ---------------------------------------------------------------------------
// Kernel 2: out = grouped_pw(g_h, w2, b2) * mask
// Grid: (T/BN, COUT/BM, B)
// ---------------------------------------------------------------------------
__global__ __launch_bounds__(256, 2)
void ffn_layer2(const float* __restrict__ xm, const float* __restrict__ w2,
                const float* __restrict__ b2, float* __restrict__ out)
{
    __shared__ float Ws[BK * SS];
    __shared__ float Hs[BK * SS];

    const int t0 = blockIdx.x * BN;
    const int m0 = blockIdx.y * BM;
    const int b  = blockIdx.z;
    const int g2 = m0 / (COUT / G_);        // 128 out-channels per group, BM==128

    const int tid = threadIdx.x;
    const int tm  = tid & 15;
    const int tn  = tid >> 4;

    const float* hg   = g_h + ((size_t)b * H_ + (size_t)g2 * K2) * T_ + t0;
    const float* mrow = xm  + (size_t)b * T_ + t0;

    float acc[8][8];
    #pragma unroll
    for (int i = 0; i < 8; i++)
        #pragma unroll
        for (int j = 0; j < 8; j++) acc[i][j] = 0.f;

    for (int kk = 0; kk < K2; kk += BK) {
        #pragma unroll
        for (int it = 0; it < 4; it++) {
            int idx = it * 256 + tid;
            int r   = idx >> 3;             // 0..127
            int c4  = idx & 7;              // 0..7
            float4 v = *(const float4*)(w2 + (size_t)(m0 + r) * K2 + kk + c4 * 4);
            Ws[(c4 * 4 + 0) * SS + r] = v.x;
            Ws[(c4 * 4 + 1) * SS + r] = v.y;
            Ws[(c4 * 4 + 2) * SS + r] = v.z;
            Ws[(c4 * 4 + 3) * SS + r] = v.w;
        }
        #pragma unroll
        for (int it = 0; it < 4; it++) {
            int idx = it * 256 + tid;
            int r   = idx >> 5;             // 0..31
            int c4  = idx & 31;             // 0..31
            float4 v = *(const float4*)(hg + (size_t)(kk + r) * T_ + c4 * 4);
            *(float4*)(Hs + r * SS + c4 * 4) = v;
        }
        __syncthreads();

        #pragma unroll
        for (int k = 0; k < BK; k++) {
            float4 a0 = *(const float4*)(Ws + k * SS + tm * 8);
            float4 a1 = *(const float4*)(Ws + k * SS + tm * 8 + 4);
            float4 c0 = *(const float4*)(Hs + k * SS + tn * 8);
            float4 c1 = *(const float4*)(Hs + k * SS + tn * 8 + 4);
            float a[8] = {a0.x, a0.y, a0.z, a0.w, a1.x, a1.y, a1.z, a1.w};
            float c[8] = {c0.x, c0.y, c0.z, c0.w, c1.x, c1.y, c1.z, c1.w};
            #pragma unroll
            for (int i = 0; i < 8; i++)
                #pragma unroll
                for (int j = 0; j < 8; j++)
                    acc[i][j] = fmaf(a[i], c[j], acc[i][j]);
        }
        __syncthreads();
    }

    // Epilogue: bias, then * mask, write out[b][m][t]
    float4 m0v = *(const float4*)(mrow + tn * 8);
    float4 m1v = *(const float4*)(mrow + tn * 8 + 4);
    float mv[8] = {m0v.x, m0v.y, m0v.z, m0v.w, m1v.x, m1v.y, m1v.z, m1v.w};

    #pragma unroll
    for (int i = 0; i < 8; i++) {
        int   m    = m0 + tm * 8 + i;
        float bias = b2[m];
        float* orow = out + ((size_t)b * COUT + m) * T_ + t0 + tn * 8;
        float v[8];
        #pragma unroll
        for (int jj = 0; jj < 8; jj++)
            v[jj] = (acc[i][jj] + bias) * mv[jj];
        *(float4*)(orow)     = make_float4(v[0], v[1], v[2], v[3]);
        *(float4*)(orow + 4) = make_float4(v[4], v[5], v[6], v[7]);
    }
}

// ---------------------------------------------------------------------------
// Launch
// ---------------------------------------------------------------------------
extern "C" void kernel_launch(void* const* d_in, const int* in_sizes, int n_in,
                              void* d_out, int out_size)
{
    const float* x  = (const float*)d_in[0];   // [B, CIN, T]
    const float* xm = (const float*)d_in[1];   // [B, 1, T]
    const float* w1 = (const float*)d_in[2];   // [H, CIN/G]
    const float* b1 = (const float*)d_in[3];   // [H]
    const float* w2 = (const float*)d_in[4];   // [COUT, H/G]
    const float* b2 = (const float*)d_in[5];   // [COUT]
    // d_in[6] = n_groups (always 4; hardcoded)

    float* out = (float*)d_out;                // [B, COUT, T]

    dim3 grid1(T_ / BN, H_ / BM, B_);
    ffn_layer1<<<grid1, 256>>>(x, xm, w1, b1);

    dim3 grid2(T_ / BN, COUT / BM, B_);
    ffn_layer2<<<grid2, 256>>>(xm, w2, b2, out);
}

// round 6
// speedup vs baseline: 2.1527x; 2.1527x over previous
#include <cuda_runtime.h>
#include <cuda_fp16.h>
#include <cstdint>
#include <math.h>

// ---------------- problem constants ----------------
#define B_    16
#define CIN   512
#define T_    2048
#define H_    2048
#define COUT  512
#define G_    4

// ---------------- tiling ----------------
#define BM 128
#define BN 128
#define BK 64            // halves per k-chunk; 64*2B = 128B = one swizzle row

// ---------------- smem (single stage, 64 KB -> 2 CTAs/SM) ----------------
#define OFF_AHI 0
#define OFF_ALO 16384
#define OFF_BHI 32768
#define OFF_BLO 49152
#define SMEM_TOTAL 65536

// SW128-style swizzle within 128B rows
#define SWZ(off) ((off) ^ (((off) >> 3) & 0x70))

// intermediate (shuffled, post-gelu), fp32 [B, H, T] = 256 MiB
__device__ float g_h[(size_t)B_ * H_ * T_];

// ---------------- PTX helpers (family-agnostic: sm_80+) ----------------
__device__ __forceinline__ uint32_t smem_to_u32(const void* p) {
    uint32_t a;
    asm("{ .reg .u64 t; cvta.to.shared.u64 t, %1; cvt.u32.u64 %0, t; }" : "=r"(a) : "l"(p));
    return a;
}
__device__ __forceinline__ void ldsm4(uint32_t* r, uint32_t addr) {
    asm volatile("ldmatrix.sync.aligned.m8n8.x4.shared.b16 {%0,%1,%2,%3}, [%4];"
        : "=r"(r[0]), "=r"(r[1]), "=r"(r[2]), "=r"(r[3]) : "r"(addr));
}
__device__ __forceinline__ void mma16816(float* c, const uint32_t* a, uint32_t b0, uint32_t b1) {
    asm volatile("mma.sync.aligned.m16n8k16.row.col.f32.f16.f16.f32 "
        "{%0,%1,%2,%3}, {%4,%5,%6,%7}, {%8,%9}, {%0,%1,%2,%3};"
        : "+f"(c[0]), "+f"(c[1]), "+f"(c[2]), "+f"(c[3])
        : "r"(a[0]), "r"(a[1]), "r"(a[2]), "r"(a[3]), "r"(b0), "r"(b1));
}

__device__ __forceinline__ float gelu_exact(float v) {
    return 0.5f * v * (1.0f + erff(v * 0.70710678118654752440f));
}

// ---------------- stagers: fp32 global -> fp16 hi/lo swizzled smem ----------------
// A (weights): [BM rows][BK k], k contiguous in gmem (row stride ldk)
__device__ __forceinline__ void load_a(const float* __restrict__ gA, int ldk,
                                       char* __restrict__ sHi, char* __restrict__ sLo, int tid)
{
    #pragma unroll
    for (int it = 0; it < 8; it++) {
        int idx = it * 256 + tid;
        int m = idx >> 4, q = idx & 15;                 // q: float4 index along k
        float4 v = *(const float4*)(gA + (size_t)m * ldk + q * 4);
        __half2 h01 = __float22half2_rn(make_float2(v.x, v.y));
        __half2 h23 = __float22half2_rn(make_float2(v.z, v.w));
        float2 f01 = __half22float2(h01);
        float2 f23 = __half22float2(h23);
        __half2 l01 = __float22half2_rn(make_float2(v.x - f01.x, v.y - f01.y));
        __half2 l23 = __float22half2_rn(make_float2(v.z - f23.x, v.w - f23.y));
        uint32_t off = SWZ((uint32_t)(m * 128 + q * 8));
        union { __half2 h[2]; uint2 u; } ph, pl;
        ph.h[0] = h01; ph.h[1] = h23;
        pl.h[0] = l01; pl.h[1] = l23;
        *(uint2*)(sHi + off) = ph.u;
        *(uint2*)(sLo + off) = pl.u;
    }
}

// B (activations): gmem [BK k rows (stride T_)][BN t], stored smem as [t row][k]
__device__ __forceinline__ void load_b(const float* __restrict__ gB, const float* __restrict__ mrow,
                                       char* __restrict__ sHi, char* __restrict__ sLo, int tid)
{
    #pragma unroll
    for (int it = 0; it < 8; it++) {
        int idx = it * 256 + tid;
        int t = idx & 127, kq = idx >> 7;               // kq: 0..15, 4 k per thread
        const float* p = gB + (size_t)(kq * 4) * T_ + t;
        float x0 = p[0];
        float x1 = p[T_];
        float x2 = p[2 * T_];
        float x3 = p[3 * T_];
        if (mrow) {
            float mk = mrow[t];
            x0 *= mk; x1 *= mk; x2 *= mk; x3 *= mk;
        }
        __half2 h01 = __float22half2_rn(make_float2(x0, x1));
        __half2 h23 = __float22half2_rn(make_float2(x2, x3));
        float2 f01 = __half22float2(h01);
        float2 f23 = __half22float2(h23);
        __half2 l01 = __float22half2_rn(make_float2(x0 - f01.x, x1 - f01.y));
        __half2 l23 = __float22half2_rn(make_float2(x2 - f23.x, x3 - f23.y));
        uint32_t off = SWZ((uint32_t)(t * 128 + kq * 8));
        union { __half2 h[2]; uint2 u; } ph, pl;
        ph.h[0] = h01; ph.h[1] = h23;
        pl.h[0] = l01; pl.h[1] = l23;
        *(uint2*)(sHi + off) = ph.u;
        *(uint2*)(sLo + off) = pl.u;
    }
}

// ---------------- shared mainloop body (one BK=64 chunk) ----------------
// acc layout: acc[mi][n8 tile 0..7][4]
__device__ __forceinline__ void mma_chunk(float acc[2][8][4], uint32_t sb,
                                          int warp_m, int warp_n, int lid)
{
    const int rA = lid & 15;
    const int cA = (lid >> 4) << 4;                          // 0 or 16 bytes
    const int rB = (lid & 7) | ((lid >> 4) << 3);            // 0..15
    const int cB = ((lid >> 3) & 1) << 4;                    // 0 or 16 bytes

    #pragma unroll
    for (int k16 = 0; k16 < 4; k16++) {
        const int kb = k16 * 32;                              // byte offset along k
        uint32_t aH[2][4], aL[2][4];
        #pragma unroll
        for (int mi = 0; mi < 2; mi++) {
            int row = warp_m * 32 + mi * 16 + rA;
            uint32_t sw  = (uint32_t)((row & 7) << 4);
            uint32_t off = (uint32_t)(row * 128) + (((uint32_t)(kb + cA)) ^ sw);
            ldsm4(aH[mi], sb + OFF_AHI + off);
            ldsm4(aL[mi], sb + OFF_ALO + off);
        }
        #pragma unroll
        for (int nj = 0; nj < 4; nj++) {
            int row = warp_n * 64 + nj * 16 + rB;
            uint32_t sw  = (uint32_t)((row & 7) << 4);
            uint32_t off = (uint32_t)(row * 128) + (((uint32_t)(kb + cB)) ^ sw);
            uint32_t bH[4], bL[4];
            ldsm4(bH, sb + OFF_BHI + off);
            ldsm4(bL, sb + OFF_BLO + off);
            #pragma unroll
            for (int h = 0; h < 2; h++) {
                uint32_t b0h = bH[h * 2], b1h = bH[h * 2 + 1];
                uint32_t b0l = bL[h * 2], b1l = bL[h * 2 + 1];
                #pragma unroll
                for (int mi = 0; mi < 2; mi++) {
                    float* d = acc[mi][nj * 2 + h];
                    mma16816(d, aH[mi], b0h, b1h);
                    mma16816(d, aH[mi], b0l, b1l);
                    mma16816(d, aL[mi], b0h, b1h);
                }
            }
        }
    }
}

// ---------------- layer 1: g_h = shuffle(gelu(W1 @ (x*mask) + b1)) ----------------
__global__ __launch_bounds__(256, 2)
void ffn_l1(const float* __restrict__ x, const float* __restrict__ xm,
            const float* __restrict__ w1, const float* __restrict__ b1)
{
    extern __shared__ char smem[];
    const uint32_t sb = smem_to_u32(smem);
    const int tid = threadIdx.x, wid = tid >> 5, lid = tid & 31;
    const int warp_m = wid >> 1, warp_n = wid & 1;
    const int t0 = blockIdx.x * BN, m0 = blockIdx.y * BM, b = blockIdx.z;
    const int g = m0 >> 9;                                   // group = m0 / 512

    const float* gA   = w1 + (size_t)m0 * 128;               // ldk = 128
    const float* gB   = x  + ((size_t)b * CIN + g * 128) * T_ + t0;
    const float* mrow = xm + (size_t)b * T_ + t0;

    float acc[2][8][4];
    #pragma unroll
    for (int i = 0; i < 2; i++)
        #pragma unroll
        for (int j = 0; j < 8; j++)
            #pragma unroll
            for (int q = 0; q < 4; q++) acc[i][j][q] = 0.f;

    #pragma unroll 1
    for (int c = 0; c < 2; c++) {                            // K=128 / BK
        load_a(gA + c * BK, 128, smem + OFF_AHI, smem + OFF_ALO, tid);
        load_b(gB + (size_t)(c * BK) * T_, mrow, smem + OFF_BHI, smem + OFF_BLO, tid);
        __syncthreads();
        mma_chunk(acc, sb, warp_m, warp_n, lid);
        __syncthreads();
    }

    // epilogue: bias + exact gelu, store channel-shuffled (cs = (m%512)*4 + g)
    const int gid = lid >> 2, qid = lid & 3;
    #pragma unroll
    for (int mi = 0; mi < 2; mi++) {
        #pragma unroll
        for (int half = 0; half < 2; half++) {
            int   m    = m0 + warp_m * 32 + mi * 16 + gid + half * 8;
            float bias = b1[m];
            int   cs   = ((m & 511) << 2) + g;
            float* orow = g_h + ((size_t)b * H_ + cs) * T_ + t0 + warp_n * 64;
            #pragma unroll
            for (int nj8 = 0; nj8 < 8; nj8++) {
                float2 o;
                o.x = gelu_exact(acc[mi][nj8][half * 2 + 0] + bias);
                o.y = gelu_exact(acc[mi][nj8][half * 2 + 1] + bias);
                *(float2*)(orow + nj8 * 8 + qid * 2) = o;
            }
        }
    }
}

// ---------------- layer 2: out = (W2 @ g_h + b2) * mask ----------------
__global__ __launch_bounds__(256, 2)
void ffn_l2(const float* __restrict__ xm, const float* __restrict__ w2,
            const float* __restrict__ b2, float* __restrict__ out)
{
    extern __shared__ char smem[];
    const uint32_t sb = smem_to_u32(smem);
    const int tid = threadIdx.x, wid = tid >> 5, lid = tid & 31;
    const int warp_m = wid >> 1, warp_n = wid & 1;
    const int t0 = blockIdx.x * BN, m0 = blockIdx.y * BM, b = blockIdx.z;
    const int g2 = blockIdx.y;                               // COUT/G == BM

    const float* gA   = w2 + (size_t)m0 * 512;               // ldk = 512
    const float* gB   = g_h + ((size_t)b * H_ + g2 * 512) * T_ + t0;
    const float* mrow = xm + (size_t)b * T_ + t0;

    float acc[2][8][4];
    #pragma unroll
    for (int i = 0; i < 2; i++)
        #pragma unroll
        for (int j = 0; j < 8; j++)
            #pragma unroll
            for (int q = 0; q < 4; q++) acc[i][j][q] = 0.f;

    #pragma unroll 1
    for (int c = 0; c < 8; c++) {                            // K=512 / BK
        load_a(gA + c * BK, 512, smem + OFF_AHI, smem + OFF_ALO, tid);
        load_b(gB + (size_t)(c * BK) * T_, (const float*)0, smem + OFF_BHI, smem + OFF_BLO, tid);
        __syncthreads();
        mma_chunk(acc, sb, warp_m, warp_n, lid);
        __syncthreads();
    }

    // epilogue: bias + mask
    const int gid = lid >> 2, qid = lid & 3;
    #pragma unroll
    for (int mi = 0; mi < 2; mi++) {
        #pragma unroll
        for (int half = 0; half < 2; half++) {
            int   m    = m0 + warp_m * 32 + mi * 16 + gid + half * 8;
            float bias = b2[m];
            float* orow = out + ((size_t)b * COUT + m) * T_ + t0 + warp_n * 64;
            const float* mr = mrow + warp_n * 64;
            #pragma unroll
            for (int nj8 = 0; nj8 < 8; nj8++) {
                float2 mk = *(const float2*)(mr + nj8 * 8 + qid * 2);
                float2 o;
                o.x = (acc[mi][nj8][half * 2 + 0] + bias) * mk.x;
                o.y = (acc[mi][nj8][half * 2 + 1] + bias) * mk.y;
                *(float2*)(orow + nj8 * 8 + qid * 2) = o;
            }
        }
    }
}

// ---------------- launch ----------------
extern "C" void kernel_launch(void* const* d_in, const int* in_sizes, int n_in,
                              void* d_out, int out_size)
{
    const float* x  = (const float*)d_in[0];
    const float* xm = (const float*)d_in[1];
    const float* w1 = (const float*)d_in[2];
    const float* b1 = (const float*)d_in[3];
    const float* w2 = (const float*)d_in[4];
    const float* b2 = (const float*)d_in[5];
    float* out = (float*)d_out;

    cudaFuncSetAttribute(ffn_l1, cudaFuncAttributeMaxDynamicSharedMemorySize, SMEM_TOTAL);
    cudaFuncSetAttribute(ffn_l2, cudaFuncAttributeMaxDynamicSharedMemorySize, SMEM_TOTAL);

    dim3 g1(T_ / BN, H_ / BM, B_);      // (16, 16, 16)
    ffn_l1<<<g1, 256, SMEM_TOTAL>>>(x, xm, w1, b1);

    dim3 g2(T_ / BN, COUT / BM, B_);    // (16, 4, 16)
    ffn_l2<<<g2, 256, SMEM_TOTAL>>>(xm, w2, b2, out);
}

// round 7
// speedup vs baseline: 2.3250x; 1.0800x over previous
#include <cuda_runtime.h>
#include <cuda_fp16.h>
#include <cstdint>
#include <math.h>

// ---------------- problem constants ----------------
#define B_    16
#define CIN   512
#define T_    2048
#define H_    2048
#define COUT  512
#define G_    4

// ---------------- tiling ----------------
#define BM 128
#define BN 128
#define BK 32            // halves per k-chunk; 32*2B = 64B rows

// ---------------- smem: 2 stages x 32KB = 64KB -> 2 CTAs/SM ----------------
#define PLANE      8192                 // 128 rows x 64B
#define OFF_AHI    0
#define OFF_ALO    8192
#define OFF_BHI    16384
#define OFF_BLO    24576
#define STAGE_BYTES 32768
#define SMEM_TOTAL  65536

// swizzle for 64B rows: XOR 16B-chunk bits [5:4] with row bits (o>>6)&3 and (o>>8)&1
__device__ __forceinline__ uint32_t swzb(uint32_t o) {
    return o ^ ((o >> 2) & 0x30) ^ ((o >> 4) & 0x10);
}
// reader-side XOR for a given row (col < 64)
__device__ __forceinline__ uint32_t rowsw(int row) {
    return (uint32_t)(((row & 3) << 4) ^ ((row & 4) << 2));
}

// intermediate (shuffled, post-gelu) fp16: [B, H, T] = 128 MiB
__device__ __half g_h[(size_t)B_ * H_ * T_];

// ---------------- PTX helpers (family-agnostic: sm_80+) ----------------
__device__ __forceinline__ uint32_t smem_to_u32(const void* p) {
    uint32_t a;
    asm("{ .reg .u64 t; cvta.to.shared.u64 t, %1; cvt.u32.u64 %0, t; }" : "=r"(a) : "l"(p));
    return a;
}
__device__ __forceinline__ void ldsm4(uint32_t* r, uint32_t addr) {
    asm volatile("ldmatrix.sync.aligned.m8n8.x4.shared.b16 {%0,%1,%2,%3}, [%4];"
        : "=r"(r[0]), "=r"(r[1]), "=r"(r[2]), "=r"(r[3]) : "r"(addr));
}
__device__ __forceinline__ void mma16816(float* c, const uint32_t* a, uint32_t b0, uint32_t b1) {
    asm volatile("mma.sync.aligned.m16n8k16.row.col.f32.f16.f16.f32 "
        "{%0,%1,%2,%3}, {%4,%5,%6,%7}, {%8,%9}, {%0,%1,%2,%3};"
        : "+f"(c[0]), "+f"(c[1]), "+f"(c[2]), "+f"(c[3])
        : "r"(a[0]), "r"(a[1]), "r"(a[2]), "r"(a[3]), "r"(b0), "r"(b1));
}

__device__ __forceinline__ float gelu_exact(float v) {
    return 0.5f * v * (1.0f + erff(v * 0.70710678118654752440f));
}

// ---------------- stagers ----------------
// A (weights, fp32): [BM rows][BK k], k contiguous (row stride ldk) -> hi/lo planes
__device__ __forceinline__ void load_a(const float* __restrict__ gA, int ldk,
                                       char* __restrict__ stg, int tid)
{
    #pragma unroll
    for (int it = 0; it < 4; it++) {
        int idx = it * 256 + tid;
        int m = idx >> 3, q = idx & 7;                  // 8 float4 per row
        float4 v = *(const float4*)(gA + (size_t)m * ldk + q * 4);
        __half2 h01 = __float22half2_rn(make_float2(v.x, v.y));
        __half2 h23 = __float22half2_rn(make_float2(v.z, v.w));
        float2 f01 = __half22float2(h01);
        float2 f23 = __half22float2(h23);
        __half2 l01 = __float22half2_rn(make_float2(v.x - f01.x, v.y - f01.y));
        __half2 l23 = __float22half2_rn(make_float2(v.z - f23.x, v.w - f23.y));
        uint32_t off = swzb((uint32_t)(m * 64 + q * 8));
        union { __half2 h[2]; uint2 u; } ph, pl;
        ph.h[0] = h01; ph.h[1] = h23;
        pl.h[0] = l01; pl.h[1] = l23;
        *(uint2*)(stg + OFF_AHI + off) = ph.u;
        *(uint2*)(stg + OFF_ALO + off) = pl.u;
    }
}

// B for layer1 (x, fp32, k-strided): gmem [BK k rows (stride T_)][128 t] -> smem [t][k] hi/lo
__device__ __forceinline__ void load_b1(const float* __restrict__ gB, const float* __restrict__ mrow,
                                        char* __restrict__ stg, int tid)
{
    #pragma unroll
    for (int it = 0; it < 4; it++) {
        int idx = it * 256 + tid;
        int t = idx & 127, kq = idx >> 7;               // kq: 0..7
        const float* p = gB + (size_t)(kq * 4) * T_ + t;
        float mk = mrow[t];
        float x0 = p[0] * mk;
        float x1 = p[T_] * mk;
        float x2 = p[2 * T_] * mk;
        float x3 = p[3 * T_] * mk;
        __half2 h01 = __float22half2_rn(make_float2(x0, x1));
        __half2 h23 = __float22half2_rn(make_float2(x2, x3));
        float2 f01 = __half22float2(h01);
        float2 f23 = __half22float2(h23);
        __half2 l01 = __float22half2_rn(make_float2(x0 - f01.x, x1 - f01.y));
        __half2 l23 = __float22half2_rn(make_float2(x2 - f23.x, x3 - f23.y));
        uint32_t off = swzb((uint32_t)(t * 64 + kq * 8));
        union { __half2 h[2]; uint2 u; } ph, pl;
        ph.h[0] = h01; ph.h[1] = h23;
        pl.h[0] = l01; pl.h[1] = l23;
        *(uint2*)(stg + OFF_BHI + off) = ph.u;
        *(uint2*)(stg + OFF_BLO + off) = pl.u;
    }
}

// B for layer2 (g_h, fp16 already): no conversion, hi plane only
__device__ __forceinline__ void load_b2(const __half* __restrict__ gB,
                                        char* __restrict__ stg, int tid)
{
    #pragma unroll
    for (int it = 0; it < 4; it++) {
        int idx = it * 256 + tid;
        int t = idx & 127, kq = idx >> 7;
        const __half* p = gB + (size_t)(kq * 4) * T_ + t;
        __half x0 = p[0];
        __half x1 = p[T_];
        __half x2 = p[2 * T_];
        __half x3 = p[3 * T_];
        uint32_t off = swzb((uint32_t)(t * 64 + kq * 8));
        union { __half2 h[2]; uint2 u; } ph;
        ph.h[0] = __halves2half2(x0, x1);
        ph.h[1] = __halves2half2(x2, x3);
        *(uint2*)(stg + OFF_BHI + off) = ph.u;
    }
}

// ---------------- mainloop body (one BK=32 chunk) ----------------
// SPLIT_B: layer1 uses hi/lo B (3 MMAs); layer2 uses hi-only B (2 MMAs)
template <bool SPLIT_B>
__device__ __forceinline__ void mma_chunk(float acc[2][8][4], uint32_t stg,
                                          int warp_m, int warp_n, int lid)
{
    const int rA = lid & 15;
    const int cA = (lid >> 4) << 4;
    const int rB = (lid & 7) | ((lid >> 4) << 3);
    const int cB = ((lid >> 3) & 1) << 4;

    #pragma unroll
    for (int k16 = 0; k16 < 2; k16++) {
        const int kb = k16 * 32;
        uint32_t aH[2][4], aL[2][4];
        #pragma unroll
        for (int mi = 0; mi < 2; mi++) {
            int row = warp_m * 32 + mi * 16 + rA;
            uint32_t off = (uint32_t)(row * 64) + (((uint32_t)(kb + cA)) ^ rowsw(row));
            ldsm4(aH[mi], stg + OFF_AHI + off);
            ldsm4(aL[mi], stg + OFF_ALO + off);
        }
        #pragma unroll
        for (int nj = 0; nj < 4; nj++) {
            int row = warp_n * 64 + nj * 16 + rB;
            uint32_t off = (uint32_t)(row * 64) + (((uint32_t)(kb + cB)) ^ rowsw(row));
            uint32_t bH[4], bL[4];
            ldsm4(bH, stg + OFF_BHI + off);
            if (SPLIT_B) ldsm4(bL, stg + OFF_BLO + off);
            #pragma unroll
            for (int h = 0; h < 2; h++) {
                #pragma unroll
                for (int mi = 0; mi < 2; mi++) {
                    float* d = acc[mi][nj * 2 + h];
                    mma16816(d, aH[mi], bH[h * 2], bH[h * 2 + 1]);
                    if (SPLIT_B) mma16816(d, aH[mi], bL[h * 2], bL[h * 2 + 1]);
                    mma16816(d, aL[mi], bH[h * 2], bH[h * 2 + 1]);
                }
            }
        }
    }
}

// ---------------- layer 1: g_h = fp16(shuffle(gelu(W1 @ (x*mask) + b1))) ----------------
__global__ __launch_bounds__(256, 2)
void ffn_l1(const float* __restrict__ x, const float* __restrict__ xm,
            const float* __restrict__ w1, const float* __restrict__ b1)
{
    extern __shared__ char smem[];
    const uint32_t sb = smem_to_u32(smem);
    const int tid = threadIdx.x, wid = tid >> 5, lid = tid & 31;
    const int warp_m = wid >> 1, warp_n = wid & 1;
    const int t0 = blockIdx.x * BN, m0 = blockIdx.y * BM, b = blockIdx.z;
    const int g = m0 >> 9;

    const float* gA   = w1 + (size_t)m0 * 128;               // ldk = 128
    const float* gB   = x  + ((size_t)b * CIN + g * 128) * T_ + t0;
    const float* mrow = xm + (size_t)b * T_ + t0;

    float acc[2][8][4];
    #pragma unroll
    for (int i = 0; i < 2; i++)
        #pragma unroll
        for (int j = 0; j < 8; j++)
            #pragma unroll
            for (int q = 0; q < 4; q++) acc[i][j][q] = 0.f;

    const int C = 4;                                         // K=128 / BK
    load_a(gA, 128, smem, tid);
    load_b1(gB, mrow, smem, tid);
    __syncthreads();
    #pragma unroll 1
    for (int c = 0; c < C; c++) {
        int s = c & 1;
        if (c + 1 < C) {
            char* nstg = smem + ((c + 1) & 1) * STAGE_BYTES;
            load_a(gA + (c + 1) * BK, 128, nstg, tid);
            load_b1(gB + (size_t)((c + 1) * BK) * T_, mrow, nstg, tid);
        }
        mma_chunk<true>(acc, sb + s * STAGE_BYTES, warp_m, warp_n, lid);
        __syncthreads();
    }

    // epilogue: bias + exact gelu -> fp16, store channel-shuffled (cs = (m%512)*4 + g)
    const int gid = lid >> 2, qid = lid & 3;
    #pragma unroll
    for (int mi = 0; mi < 2; mi++) {
        #pragma unroll
        for (int half = 0; half < 2; half++) {
            int   m    = m0 + warp_m * 32 + mi * 16 + gid + half * 8;
            float bias = b1[m];
            int   cs   = ((m & 511) << 2) + g;
            __half* orow = g_h + ((size_t)b * H_ + cs) * T_ + t0 + warp_n * 64;
            #pragma unroll
            for (int nj8 = 0; nj8 < 8; nj8++) {
                float ox = gelu_exact(acc[mi][nj8][half * 2 + 0] + bias);
                float oy = gelu_exact(acc[mi][nj8][half * 2 + 1] + bias);
                *(__half2*)(orow + nj8 * 8 + qid * 2) = __float22half2_rn(make_float2(ox, oy));
            }
        }
    }
}

// ---------------- layer 2: out = (W2 @ g_h + b2) * mask ----------------
__global__ __launch_bounds__(256, 2)
void ffn_l2(const float* __restrict__ xm, const float* __restrict__ w2,
            const float* __restrict__ b2, float* __restrict__ out)
{
    extern __shared__ char smem[];
    const uint32_t sb = smem_to_u32(smem);
    const int tid = threadIdx.x, wid = tid >> 5, lid = tid & 31;
    const int warp_m = wid >> 1, warp_n = wid & 1;
    const int t0 = blockIdx.x * BN, m0 = blockIdx.y * BM, b = blockIdx.z;
    const int g2 = blockIdx.y;                               // COUT/G == BM

    const float* gA  = w2 + (size_t)m0 * 512;                // ldk = 512
    const __half* gB = g_h + ((size_t)b * H_ + g2 * 512) * T_ + t0;
    const float* mrow = xm + (size_t)b * T_ + t0;

    float acc[2][8][4];
    #pragma unroll
    for (int i = 0; i < 2; i++)
        #pragma unroll
        for (int j = 0; j < 8; j++)
            #pragma unroll
            for (int q = 0; q < 4; q++) acc[i][j][q] = 0.f;

    const int C = 16;                                        // K=512 / BK
    load_a(gA, 512, smem, tid);
    load_b2(gB, smem, tid);
    __syncthreads();
    #pragma unroll 1
    for (int c = 0; c < C; c++) {
        int s = c & 1;
        if (c + 1 < C) {
            char* nstg = smem + ((c + 1) & 1) * STAGE_BYTES;
            load_a(gA + (c + 1) * BK, 512, nstg, tid);
            load_b2(gB + (size_t)((c + 1) * BK) * T_, nstg, tid);
        }
        mma_chunk<false>(acc, sb + s * STAGE_BYTES, warp_m, warp_n, lid);
        __syncthreads();
    }

    // epilogue: bias + mask
    const int gid = lid >> 2, qid = lid & 3;
    #pragma unroll
    for (int mi = 0; mi < 2; mi++) {
        #pragma unroll
        for (int half = 0; half < 2; half++) {
            int   m    = m0 + warp_m * 32 + mi * 16 + gid + half * 8;
            float bias = b2[m];
            float* orow = out + ((size_t)b * COUT + m) * T_ + t0 + warp_n * 64;
            const float* mr = mrow + warp_n * 64;
            #pragma unroll
            for (int nj8 = 0; nj8 < 8; nj8++) {
                float2 mk = *(const float2*)(mr + nj8 * 8 + qid * 2);
                float2 o;
                o.x = (acc[mi][nj8][half * 2 + 0] + bias) * mk.x;
                o.y = (acc[mi][nj8][half * 2 + 1] + bias) * mk.y;
                *(float2*)(orow + nj8 * 8 + qid * 2) = o;
            }
        }
    }
}

// ---------------- launch ----------------
extern "C" void kernel_launch(void* const* d_in, const int* in_sizes, int n_in,
                              void* d_out, int out_size)
{
    const float* x  = (const float*)d_in[0];
    const float* xm = (const float*)d_in[1];
    const float* w1 = (const float*)d_in[2];
    const float* b1 = (const float*)d_in[3];
    const float* w2 = (const float*)d_in[4];
    const float* b2 = (const float*)d_in[5];
    float* out = (float*)d_out;

    cudaFuncSetAttribute(ffn_l1, cudaFuncAttributeMaxDynamicSharedMemorySize, SMEM_TOTAL);
    cudaFuncSetAttribute(ffn_l2, cudaFuncAttributeMaxDynamicSharedMemorySize, SMEM_TOTAL);

    dim3 g1(T_ / BN, H_ / BM, B_);      // (16, 16, 16)
    ffn_l1<<<g1, 256, SMEM_TOTAL>>>(x, xm, w1, b1);

    dim3 g2(T_ / BN, COUT / BM, B_);    // (16, 4, 16)
    ffn_l2<<<g2, 256, SMEM_TOTAL>>>(xm, w2, b2, out);
}

// round 8
// speedup vs baseline: 3.6672x; 1.5772x over previous
#include <cuda_runtime.h>
#include <cuda_fp16.h>
#include <cstdint>
#include <math.h>

// ---------------- problem constants ----------------
#define B_    16
#define CIN   512
#define T_    2048
#define H_    2048
#define COUT  512
#define G_    4

// ---------------- tiling ----------------
#define BM 128
#define BN 128
#define BK 32

// ---------------- smem: 4 stages x 24KB = 96KB -> 2 CTAs/SM ----------------
#define SA_HI 0            // 128 rows x 64B
#define SA_LO 8192
#define SB    16384        // 32 k-rows x 256B
#define STAGE 24576
#define NSTG  4
#define SMEM_TOTAL (STAGE * NSTG)   // 98304

// A-plane swizzle (64B rows)
__device__ __forceinline__ uint32_t swzb(uint32_t o) {
    return o ^ ((o >> 2) & 0x30) ^ ((o >> 4) & 0x10);
}
__device__ __forceinline__ uint32_t rowsw(int row) {
    return (uint32_t)(((row & 3) << 4) ^ ((row & 4) << 2));
}

// ---------------- device scratch (pre-converted operands) ----------------
__device__ __half g_w1h[(size_t)H_ * 128];
__device__ __half g_w1l[(size_t)H_ * 128];
__device__ __half g_w2h[(size_t)COUT * 512];
__device__ __half g_w2l[(size_t)COUT * 512];
__device__ __half g_xh[(size_t)B_ * CIN * T_];      // x*mask, fp16
__device__ __half g_h [(size_t)B_ * H_  * T_];      // shuffled gelu output, fp16

// ---------------- PTX helpers (sm_80+ family-agnostic) ----------------
__device__ __forceinline__ uint32_t smem_to_u32(const void* p) {
    uint32_t a;
    asm("{ .reg .u64 t; cvta.to.shared.u64 t, %1; cvt.u32.u64 %0, t; }" : "=r"(a) : "l"(p));
    return a;
}
__device__ __forceinline__ void ldsm4(uint32_t* r, uint32_t addr) {
    asm volatile("ldmatrix.sync.aligned.m8n8.x4.shared.b16 {%0,%1,%2,%3}, [%4];"
        : "=r"(r[0]), "=r"(r[1]), "=r"(r[2]), "=r"(r[3]) : "r"(addr));
}
__device__ __forceinline__ void ldsm4t(uint32_t* r, uint32_t addr) {
    asm volatile("ldmatrix.sync.aligned.m8n8.x4.trans.shared.b16 {%0,%1,%2,%3}, [%4];"
        : "=r"(r[0]), "=r"(r[1]), "=r"(r[2]), "=r"(r[3]) : "r"(addr));
}
__device__ __forceinline__ void mma16816(float* c, const uint32_t* a, uint32_t b0, uint32_t b1) {
    asm volatile("mma.sync.aligned.m16n8k16.row.col.f32.f16.f16.f32 "
        "{%0,%1,%2,%3}, {%4,%5,%6,%7}, {%8,%9}, {%0,%1,%2,%3};"
        : "+f"(c[0]), "+f"(c[1]), "+f"(c[2]), "+f"(c[3])
        : "r"(a[0]), "r"(a[1]), "r"(a[2]), "r"(a[3]), "r"(b0), "r"(b1));
}
__device__ __forceinline__ void cpa16(uint32_t dst, const __half* src) {
    asm volatile("cp.async.cg.shared.global [%0], [%1], 16;"
        :: "r"(dst), "l"(__cvta_generic_to_global(src)));
}
#define CP_COMMIT()  asm volatile("cp.async.commit_group;" ::: "memory")
#define CP_WAIT(n)   asm volatile("cp.async.wait_group %0;" :: "n"(n) : "memory")

__device__ __forceinline__ float gelu_tanh(float v) {
    // 0.79788456*0.044715 = 0.03567740814
    float u = v * (0.7978845608028654f + 0.03567740814f * v * v);
    float t;
    asm("tanh.approx.f32 %0, %1;" : "=f"(t) : "f"(u));
    return 0.5f * v * (1.0f + t);
}

// ---------------- prologue kernels ----------------
__device__ __forceinline__ void split_hilo(float4 v, uint2& hi, uint2& lo) {
    __half2 h01 = __float22half2_rn(make_float2(v.x, v.y));
    __half2 h23 = __float22half2_rn(make_float2(v.z, v.w));
    float2 f01 = __half22float2(h01);
    float2 f23 = __half22float2(h23);
    __half2 l01 = __float22half2_rn(make_float2(v.x - f01.x, v.y - f01.y));
    __half2 l23 = __float22half2_rn(make_float2(v.z - f23.x, v.w - f23.y));
    union { __half2 h[2]; uint2 u; } p;
    p.h[0] = h01; p.h[1] = h23; hi = p.u;
    p.h[0] = l01; p.h[1] = l23; lo = p.u;
}

__global__ void prep_w(const float* __restrict__ w1, const float* __restrict__ w2) {
    int i = blockIdx.x * 256 + threadIdx.x;              // 0..65535 float4s each
    uint2 hi, lo;
    split_hilo(((const float4*)w1)[i], hi, lo);
    ((uint2*)g_w1h)[i] = hi;
    ((uint2*)g_w1l)[i] = lo;
    split_hilo(((const float4*)w2)[i], hi, lo);
    ((uint2*)g_w2h)[i] = hi;
    ((uint2*)g_w2l)[i] = lo;
}

__global__ void prep_x(const float* __restrict__ x, const float* __restrict__ xm) {
    size_t i = (size_t)blockIdx.x * 256 + threadIdx.x;   // float4 index
    size_t e = i * 4;
    int t = (int)(e & (T_ - 1));
    int b = (int)(e >> 20);                              // CIN*T_ = 2^20
    float4 v = ((const float4*)x)[i];
    float4 mk = *(const float4*)(xm + (size_t)b * T_ + t);
    v.x *= mk.x; v.y *= mk.y; v.z *= mk.z; v.w *= mk.w;
    union { __half2 h[2]; uint2 u; } p;
    p.h[0] = __float22half2_rn(make_float2(v.x, v.y));
    p.h[1] = __float22half2_rn(make_float2(v.z, v.w));
    ((uint2*)g_xh)[i] = p.u;
}

// ---------------- stage prefetch: pure cp.async ----------------
__device__ __forceinline__ void prefetch(uint32_t stg, const __half* Ah, const __half* Al,
                                         const __half* Bg, int ldk, int tid)
{
    #pragma unroll
    for (int it = 0; it < 2; it++) {
        int idx = it * 256 + tid;
        int m = idx >> 2, q = idx & 3;                   // 4x16B per A row
        uint32_t d = stg + SA_HI + swzb((uint32_t)(m * 64 + q * 16));
        const size_t so = (size_t)m * ldk + q * 8;
        cpa16(d, Ah + so);
        cpa16(d + (SA_LO - SA_HI), Al + so);
    }
    #pragma unroll
    for (int it = 0; it < 2; it++) {
        int idx = it * 256 + tid;
        int k = idx >> 4, tc = idx & 15;                 // 16x16B per B k-row
        uint32_t d = stg + SB + (uint32_t)(k * 256) + (((uint32_t)(tc * 16)) ^ ((uint32_t)(k & 7) << 4));
        cpa16(d, Bg + (size_t)k * T_ + tc * 8);
    }
}

// ---------------- mainloop body: one BK=32 chunk, A hi/lo x B single ----------------
__device__ __forceinline__ void mma_chunk2(float acc[2][8][4], uint32_t stg,
                                           int warp_m, int warp_n, int lid)
{
    const int rA = lid & 15;
    const int cA = (lid >> 4) << 4;
    const int kB = lid & 15;
    const uint32_t nbyte = (uint32_t)(warp_n * 128 + ((lid >> 4) << 4));

    #pragma unroll
    for (int k16 = 0; k16 < 2; k16++) {
        uint32_t aH[2][4], aL[2][4];
        #pragma unroll
        for (int mi = 0; mi < 2; mi++) {
            int row = warp_m * 32 + mi * 16 + rA;
            uint32_t off = (uint32_t)(row * 64) + (((uint32_t)(k16 * 32 + cA)) ^ rowsw(row));
            ldsm4(aH[mi], stg + SA_HI + off);
            ldsm4(aL[mi], stg + SA_LO + off);
        }
        int krow = k16 * 16 + kB;
        uint32_t baddr = stg + SB + (uint32_t)(krow * 256);
        uint32_t bsw   = ((uint32_t)(krow & 7)) << 4;
        #pragma unroll
        for (int nj = 0; nj < 4; nj++) {
            uint32_t bT[4];
            ldsm4t(bT, baddr + ((nbyte + (uint32_t)(nj * 32)) ^ bsw));
            #pragma unroll
            for (int h = 0; h < 2; h++)
                #pragma unroll
                for (int mi = 0; mi < 2; mi++) {
                    float* d = acc[mi][nj * 2 + h];
                    mma16816(d, aH[mi], bT[h * 2], bT[h * 2 + 1]);
                    mma16816(d, aL[mi], bT[h * 2], bT[h * 2 + 1]);
                }
        }
    }
}

// ---------------- shared GEMM mainloop (C chunks, 4-stage cp.async ring) ----------------
__device__ __forceinline__ void gemm_loop(float acc[2][8][4], char* smem, uint32_t sb,
                                          const __half* Ah, const __half* Al, int ldk,
                                          const __half* Bg, int C,
                                          int tid, int warp_m, int warp_n, int lid)
{
    for (int s = 0; s < 3 && s < C; s++) {
        prefetch(sb + s * STAGE, Ah + s * BK, Al + s * BK, Bg + (size_t)(s * BK) * T_, ldk, tid);
        CP_COMMIT();
    }
    #pragma unroll 1
    for (int c = 0; c < C; c++) {
        if (c + 3 < C) {
            int s = (c + 3) & 3;
            prefetch(sb + s * STAGE, Ah + (c + 3) * BK, Al + (c + 3) * BK,
                     Bg + (size_t)((c + 3) * BK) * T_, ldk, tid);
            CP_COMMIT();
        }
        int ahead = C - 1 - c;
        if (ahead >= 3)      CP_WAIT(3);
        else if (ahead == 2) CP_WAIT(2);
        else if (ahead == 1) CP_WAIT(1);
        else                 CP_WAIT(0);
        __syncthreads();
        mma_chunk2(acc, sb + (c & 3) * STAGE, warp_m, warp_n, lid);
        __syncthreads();
    }
}

// ---------------- layer 1: g_h = fp16(shuffle(gelu(W1 @ (x*mask) + b1))) ----------------
__global__ __launch_bounds__(256, 2)
void ffn_l1(const float* __restrict__ b1)
{
    extern __shared__ char smem[];
    const uint32_t sb = smem_to_u32(smem);
    const int tid = threadIdx.x, wid = tid >> 5, lid = tid & 31;
    const int warp_m = wid >> 1, warp_n = wid & 1;
    const int t0 = blockIdx.x * BN, m0 = blockIdx.y * BM, b = blockIdx.z;
    const int g = m0 >> 9;

    const __half* Ah = g_w1h + (size_t)m0 * 128;
    const __half* Al = g_w1l + (size_t)m0 * 128;
    const __half* Bg = g_xh + ((size_t)b * CIN + g * 128) * T_ + t0;

    float acc[2][8][4];
    #pragma unroll
    for (int i = 0; i < 2; i++)
        #pragma unroll
        for (int j = 0; j < 8; j++)
            #pragma unroll
            for (int q = 0; q < 4; q++) acc[i][j][q] = 0.f;

    gemm_loop(acc, smem, sb, Ah, Al, 128, Bg, 4, tid, warp_m, warp_n, lid);

    // epilogue: bias + gelu(tanh HW) -> fp16, channel-shuffled (cs = (m%512)*4 + g)
    const int gid = lid >> 2, qid = lid & 3;
    #pragma unroll
    for (int mi = 0; mi < 2; mi++) {
        #pragma unroll
        for (int half = 0; half < 2; half++) {
            int   m    = m0 + warp_m * 32 + mi * 16 + gid + half * 8;
            float bias = b1[m];
            int   cs   = ((m & 511) << 2) + g;
            __half* orow = g_h + ((size_t)b * H_ + cs) * T_ + t0 + warp_n * 64;
            #pragma unroll
            for (int nj8 = 0; nj8 < 8; nj8++) {
                float ox = gelu_tanh(acc[mi][nj8][half * 2 + 0] + bias);
                float oy = gelu_tanh(acc[mi][nj8][half * 2 + 1] + bias);
                *(__half2*)(orow + nj8 * 8 + qid * 2) = __float22half2_rn(make_float2(ox, oy));
            }
        }
    }
}

// ---------------- layer 2: out = (W2 @ g_h + b2) * mask ----------------
__global__ __launch_bounds__(256, 2)
void ffn_l2(const float* __restrict__ xm, const float* __restrict__ b2,
            float* __restrict__ out)
{
    extern __shared__ char smem[];
    const uint32_t sb = smem_to_u32(smem);
    const int tid = threadIdx.x, wid = tid >> 5, lid = tid & 31;
    const int warp_m = wid >> 1, warp_n = wid & 1;
    const int t0 = blockIdx.x * BN, m0 = blockIdx.y * BM, b = blockIdx.z;
    const int g2 = blockIdx.y;

    const __half* Ah = g_w2h + (size_t)m0 * 512;
    const __half* Al = g_w2l + (size_t)m0 * 512;
    const __half* Bg = g_h + ((size_t)b * H_ + g2 * 512) * T_ + t0;
    const float* mrow = xm + (size_t)b * T_ + t0;

    float acc[2][8][4];
    #pragma unroll
    for (int i = 0; i < 2; i++)
        #pragma unroll
        for (int j = 0; j < 8; j++)
            #pragma unroll
            for (int q = 0; q < 4; q++) acc[i][j][q] = 0.f;

    gemm_loop(acc, smem, sb, Ah, Al, 512, Bg, 16, tid, warp_m, warp_n, lid);

    // epilogue: bias + mask
    const int gid = lid >> 2, qid = lid & 3;
    #pragma unroll
    for (int mi = 0; mi < 2; mi++) {
        #pragma unroll
        for (int half = 0; half < 2; half++) {
            int   m    = m0 + warp_m * 32 + mi * 16 + gid + half * 8;
            float bias = b2[m];
            float* orow = out + ((size_t)b * COUT + m) * T_ + t0 + warp_n * 64;
            const float* mr = mrow + warp_n * 64;
            #pragma unroll
            for (int nj8 = 0; nj8 < 8; nj8++) {
                float2 mk = *(const float2*)(mr + nj8 * 8 + qid * 2);
                float2 o;
                o.x = (acc[mi][nj8][half * 2 + 0] + bias) * mk.x;
                o.y = (acc[mi][nj8][half * 2 + 1] + bias) * mk.y;
                *(float2*)(orow + nj8 * 8 + qid * 2) = o;
            }
        }
    }
}

// ---------------- launch ----------------
extern "C" void kernel_launch(void* const* d_in, const int* in_sizes, int n_in,
                              void* d_out, int out_size)
{
    const float* x  = (const float*)d_in[0];
    const float* xm = (const float*)d_in[1];
    const float* w1 = (const float*)d_in[2];
    const float* b1 = (const float*)d_in[3];
    const float* w2 = (const float*)d_in[4];
    const float* b2 = (const float*)d_in[5];
    float* out = (float*)d_out;

    cudaFuncSetAttribute(ffn_l1, cudaFuncAttributeMaxDynamicSharedMemorySize, SMEM_TOTAL);
    cudaFuncSetAttribute(ffn_l2, cudaFuncAttributeMaxDynamicSharedMemorySize, SMEM_TOTAL);

    prep_w<<<256, 256>>>(w1, w2);                        // 65536 float4 per tensor
    prep_x<<<16384, 256>>>(x, xm);                       // 4.19M float4

    dim3 g1(T_ / BN, H_ / BM, B_);      // (16, 16, 16)
    ffn_l1<<<g1, 256, SMEM_TOTAL>>>(b1);

    dim3 g2(T_ / BN, COUT / BM, B_);    // (16, 4, 16)
    ffn_l2<<<g2, 256, SMEM_TOTAL>>>(xm, b2, out);
}

// round 9
// speedup vs baseline: 5.1122x; 1.3940x over previous
#include <cuda_runtime.h>
#include <cuda_fp16.h>
#include <cstdint>
#include <math.h>

// ---------------- problem constants ----------------
#define B_    16
#define CIN   512
#define T_    2048
#define H_    2048
#define COUT  512
#define G_    4

// ---------------- tiling ----------------
#define BM 128
#define BN 128
#define BK 32

// ---------------- smem: 6 stages x 16KB = 96KB -> 2 CTAs/SM ----------------
#define SA    0            // 128 rows x 64B  (A fp16)
#define SB    8192         // 32 k-rows x 256B (B fp16)
#define STAGE 16384
#define NSTG  6
#define SMEM_TOTAL (STAGE * NSTG)   // 98304

// A-plane swizzle (64B rows)
__device__ __forceinline__ uint32_t swzb(uint32_t o) {
    return o ^ ((o >> 2) & 0x30) ^ ((o >> 4) & 0x10);
}
__device__ __forceinline__ uint32_t rowsw(int row) {
    return (uint32_t)(((row & 3) << 4) ^ ((row & 4) << 2));
}

// ---------------- device scratch (pre-converted operands) ----------------
__device__ __half g_w1h[(size_t)H_ * 128];
__device__ __half g_w2h[(size_t)COUT * 512];
__device__ __half g_xh[(size_t)B_ * CIN * T_];      // x*mask, fp16
__device__ __half g_h [(size_t)B_ * H_  * T_];      // shuffled gelu output, fp16

// ---------------- PTX helpers (sm_80+ family-agnostic) ----------------
__device__ __forceinline__ uint32_t smem_to_u32(const void* p) {
    uint32_t a;
    asm("{ .reg .u64 t; cvta.to.shared.u64 t, %1; cvt.u32.u64 %0, t; }" : "=r"(a) : "l"(p));
    return a;
}
__device__ __forceinline__ void ldsm4(uint32_t* r, uint32_t addr) {
    asm volatile("ldmatrix.sync.aligned.m8n8.x4.shared.b16 {%0,%1,%2,%3}, [%4];"
        : "=r"(r[0]), "=r"(r[1]), "=r"(r[2]), "=r"(r[3]) : "r"(addr));
}
__device__ __forceinline__ void ldsm4t(uint32_t* r, uint32_t addr) {
    asm volatile("ldmatrix.sync.aligned.m8n8.x4.trans.shared.b16 {%0,%1,%2,%3}, [%4];"
        : "=r"(r[0]), "=r"(r[1]), "=r"(r[2]), "=r"(r[3]) : "r"(addr));
}
__device__ __forceinline__ void mma16816(float* c, const uint32_t* a, uint32_t b0, uint32_t b1) {
    asm volatile("mma.sync.aligned.m16n8k16.row.col.f32.f16.f16.f32 "
        "{%0,%1,%2,%3}, {%4,%5,%6,%7}, {%8,%9}, {%0,%1,%2,%3};"
        : "+f"(c[0]), "+f"(c[1]), "+f"(c[2]), "+f"(c[3])
        : "r"(a[0]), "r"(a[1]), "r"(a[2]), "r"(a[3]), "r"(b0), "r"(b1));
}
__device__ __forceinline__ void cpa16(uint32_t dst, const __half* src) {
    asm volatile("cp.async.cg.shared.global [%0], [%1], 16;"
        :: "r"(dst), "l"(__cvta_generic_to_global(src)));
}
#define CP_COMMIT()  asm volatile("cp.async.commit_group;" ::: "memory")
#define CP_WAIT(n)   asm volatile("cp.async.wait_group %0;" :: "n"(n) : "memory")

__device__ __forceinline__ float gelu_tanh(float v) {
    float u = v * (0.7978845608028654f + 0.03567740814f * v * v);
    float t;
    asm("tanh.approx.f32 %0, %1;" : "=f"(t) : "f"(u));
    return 0.5f * v * (1.0f + t);
}

// ---------------- prologue kernels ----------------
__global__ void prep_w(const float* __restrict__ w1, const float* __restrict__ w2) {
    int i = blockIdx.x * 256 + threadIdx.x;              // 65536 float4s each
    union { __half2 h[2]; uint2 u; } p;
    float4 v = ((const float4*)w1)[i];
    p.h[0] = __float22half2_rn(make_float2(v.x, v.y));
    p.h[1] = __float22half2_rn(make_float2(v.z, v.w));
    ((uint2*)g_w1h)[i] = p.u;
    v = ((const float4*)w2)[i];
    p.h[0] = __float22half2_rn(make_float2(v.x, v.y));
    p.h[1] = __float22half2_rn(make_float2(v.z, v.w));
    ((uint2*)g_w2h)[i] = p.u;
}

__global__ void prep_x(const float* __restrict__ x, const float* __restrict__ xm) {
    size_t i = (size_t)blockIdx.x * 256 + threadIdx.x;   // float4 index
    size_t e = i * 4;
    int t = (int)(e & (T_ - 1));
    int b = (int)(e >> 20);                              // CIN*T_ = 2^20
    float4 v = ((const float4*)x)[i];
    float4 mk = *(const float4*)(xm + (size_t)b * T_ + t);
    v.x *= mk.x; v.y *= mk.y; v.z *= mk.z; v.w *= mk.w;
    union { __half2 h[2]; uint2 u; } p;
    p.h[0] = __float22half2_rn(make_float2(v.x, v.y));
    p.h[1] = __float22half2_rn(make_float2(v.z, v.w));
    ((uint2*)g_xh)[i] = p.u;
}

// ---------------- stage prefetch: pure cp.async (4 x 16B per thread) ----------------
__device__ __forceinline__ void prefetch(uint32_t stg, const __half* Ag,
                                         const __half* Bg, int ldk, int tid)
{
    #pragma unroll
    for (int it = 0; it < 2; it++) {
        int idx = it * 256 + tid;
        int m = idx >> 2, q = idx & 3;                   // 4x16B per A row
        uint32_t d = stg + SA + swzb((uint32_t)(m * 64 + q * 16));
        cpa16(d, Ag + (size_t)m * ldk + q * 8);
    }
    #pragma unroll
    for (int it = 0; it < 2; it++) {
        int idx = it * 256 + tid;
        int k = idx >> 4, tc = idx & 15;                 // 16x16B per B k-row
        uint32_t d = stg + SB + (uint32_t)(k * 256) + (((uint32_t)(tc * 16)) ^ ((uint32_t)(k & 7) << 4));
        cpa16(d, Bg + (size_t)k * T_ + tc * 8);
    }
}

// ---------------- mainloop body: one BK=32 chunk, single A x single B ----------------
__device__ __forceinline__ void mma_chunk1(float acc[2][8][4], uint32_t stg,
                                           int warp_m, int warp_n, int lid)
{
    const int rA = lid & 15;
    const int cA = (lid >> 4) << 4;
    const int kB = lid & 15;
    const uint32_t nbyte = (uint32_t)(warp_n * 128 + ((lid >> 4) << 4));

    #pragma unroll
    for (int k16 = 0; k16 < 2; k16++) {
        uint32_t aH[2][4];
        #pragma unroll
        for (int mi = 0; mi < 2; mi++) {
            int row = warp_m * 32 + mi * 16 + rA;
            uint32_t off = (uint32_t)(row * 64) + (((uint32_t)(k16 * 32 + cA)) ^ rowsw(row));
            ldsm4(aH[mi], stg + SA + off);
        }
        int krow = k16 * 16 + kB;
        uint32_t baddr = stg + SB + (uint32_t)(krow * 256);
        uint32_t bsw   = ((uint32_t)(krow & 7)) << 4;
        #pragma unroll
        for (int nj = 0; nj < 4; nj++) {
            uint32_t bT[4];
            ldsm4t(bT, baddr + ((nbyte + (uint32_t)(nj * 32)) ^ bsw));
            #pragma unroll
            for (int h = 0; h < 2; h++)
                #pragma unroll
                for (int mi = 0; mi < 2; mi++)
                    mma16816(acc[mi][nj * 2 + h], aH[mi], bT[h * 2], bT[h * 2 + 1]);
        }
    }
}

// ---------------- shared GEMM mainloop: C chunks, 6-stage ring, distance 4 ----------------
__device__ __forceinline__ void gemm_loop(float acc[2][8][4], uint32_t sb,
                                          const __half* Ag, int ldk,
                                          const __half* Bg, int C,
                                          int tid, int warp_m, int warp_n, int lid)
{
    int wstg = 0;
    const int PF = (C < 4) ? C : 4;
    for (int s = 0; s < PF; s++) {
        prefetch(sb + wstg * STAGE, Ag + s * BK, Bg + (size_t)(s * BK) * T_, ldk, tid);
        CP_COMMIT();
        if (++wstg == NSTG) wstg = 0;
    }
    int rstg = 0;
    #pragma unroll 1
    for (int c = 0; c < C; c++) {
        if (c + 4 < C) {
            prefetch(sb + wstg * STAGE, Ag + (c + 4) * BK,
                     Bg + (size_t)((c + 4) * BK) * T_, ldk, tid);
            CP_COMMIT();
            if (++wstg == NSTG) wstg = 0;
        }
        int ahead = C - 1 - c;
        if (ahead >= 4)      CP_WAIT(4);
        else if (ahead == 3) CP_WAIT(3);
        else if (ahead == 2) CP_WAIT(2);
        else if (ahead == 1) CP_WAIT(1);
        else                 CP_WAIT(0);
        __syncthreads();
        mma_chunk1(acc, sb + rstg * STAGE, warp_m, warp_n, lid);
        if (++rstg == NSTG) rstg = 0;
    }
}

// ---------------- layer 1: g_h = fp16(shuffle(gelu(W1 @ (x*mask) + b1))) ----------------
__global__ __launch_bounds__(256, 2)
void ffn_l1(const float* __restrict__ b1)
{
    extern __shared__ char smem[];
    const uint32_t sb = smem_to_u32(smem);
    const int tid = threadIdx.x, wid = tid >> 5, lid = tid & 31;
    const int warp_m = wid >> 1, warp_n = wid & 1;
    const int t0 = blockIdx.x * BN, m0 = blockIdx.y * BM, b = blockIdx.z;
    const int g = m0 >> 9;

    const __half* Ag = g_w1h + (size_t)m0 * 128;
    const __half* Bg = g_xh + ((size_t)b * CIN + g * 128) * T_ + t0;

    float acc[2][8][4];
    #pragma unroll
    for (int i = 0; i < 2; i++)
        #pragma unroll
        for (int j = 0; j < 8; j++)
            #pragma unroll
            for (int q = 0; q < 4; q++) acc[i][j][q] = 0.f;

    gemm_loop(acc, sb, Ag, 128, Bg, 4, tid, warp_m, warp_n, lid);

    // epilogue: bias + gelu(tanh HW) -> fp16, channel-shuffled (cs = (m%512)*4 + g)
    const int gid = lid >> 2, qid = lid & 3;
    #pragma unroll
    for (int mi = 0; mi < 2; mi++) {
        #pragma unroll
        for (int half = 0; half < 2; half++) {
            int   m    = m0 + warp_m * 32 + mi * 16 + gid + half * 8;
            float bias = b1[m];
            int   cs   = ((m & 511) << 2) + g;
            __half* orow = g_h + ((size_t)b * H_ + cs) * T_ + t0 + warp_n * 64;
            #pragma unroll
            for (int nj8 = 0; nj8 < 8; nj8++) {
                float ox = gelu_tanh(acc[mi][nj8][half * 2 + 0] + bias);
                float oy = gelu_tanh(acc[mi][nj8][half * 2 + 1] + bias);
                *(__half2*)(orow + nj8 * 8 + qid * 2) = __float22half2_rn(make_float2(ox, oy));
            }
        }
    }
}

// ---------------- layer 2: out = (W2 @ g_h + b2) * mask ----------------
__global__ __launch_bounds__(256, 2)
void ffn_l2(const float* __restrict__ xm, const float* __restrict__ b2,
            float* __restrict__ out)
{
    extern __shared__ char smem[];
    const uint32_t sb = smem_to_u32(smem);
    const int tid = threadIdx.x, wid = tid >> 5, lid = tid & 31;
    const int warp_m = wid >> 1, warp_n = wid & 1;
    const int t0 = blockIdx.x * BN, m0 = blockIdx.y * BM, b = blockIdx.z;
    const int g2 = blockIdx.y;

    const __half* Ag = g_w2h + (size_t)m0 * 512;
    const __half* Bg = g_h + ((size_t)b * H_ + g2 * 512) * T_ + t0;
    const float* mrow = xm + (size_t)b * T_ + t0;

    float acc[2][8][4];
    #pragma unroll
    for (int i = 0; i < 2; i++)
        #pragma unroll
        for (int j = 0; j < 8; j++)
            #pragma unroll
            for (int q = 0; q < 4; q++) acc[i][j][q] = 0.f;

    gemm_loop(acc, sb, Ag, 512, Bg, 16, tid, warp_m, warp_n, lid);

    // epilogue: bias + mask
    const int gid = lid >> 2, qid = lid & 3;
    #pragma unroll
    for (int mi = 0; mi < 2; mi++) {
        #pragma unroll
        for (int half = 0; half < 2; half++) {
            int   m    = m0 + warp_m * 32 + mi * 16 + gid + half * 8;
            float bias = b2[m];
            float* orow = out + ((size_t)b * COUT + m) * T_ + t0 + warp_n * 64;
            const float* mr = mrow + warp_n * 64;
            #pragma unroll
            for (int nj8 = 0; nj8 < 8; nj8++) {
                float2 mk = *(const float2*)(mr + nj8 * 8 + qid * 2);
                float2 o;
                o.x = (acc[mi][nj8][half * 2 + 0] + bias) * mk.x;
                o.y = (acc[mi][nj8][half * 2 + 1] + bias) * mk.y;
                *(float2*)(orow + nj8 * 8 + qid * 2) = o;
            }
        }
    }
}

// ---------------- launch ----------------
extern "C" void kernel_launch(void* const* d_in, const int* in_sizes, int n_in,
                              void* d_out, int out_size)
{
    const float* x  = (const float*)d_in[0];
    const float* xm = (const float*)d_in[1];
    const float* w1 = (const float*)d_in[2];
    const float* b1 = (const float*)d_in[3];
    const float* w2 = (const float*)d_in[4];
    const float* b2 = (const float*)d_in[5];
    float* out = (float*)d_out;

    cudaFuncSetAttribute(ffn_l1, cudaFuncAttributeMaxDynamicSharedMemorySize, SMEM_TOTAL);
    cudaFuncSetAttribute(ffn_l2, cudaFuncAttributeMaxDynamicSharedMemorySize, SMEM_TOTAL);

    prep_w<<<256, 256>>>(w1, w2);
    prep_x<<<16384, 256>>>(x, xm);

    dim3 g1(T_ / BN, H_ / BM, B_);      // (16, 16, 16)
    ffn_l1<<<g1, 256, SMEM_TOTAL>>>(b1);

    dim3 g2(T_ / BN, COUT / BM, B_);    // (16, 4, 16)
    ffn_l2<<<g2, 256, SMEM_TOTAL>>>(xm, b2, out);
}